// round 1
// baseline (speedup 1.0000x reference)
#include <cuda_runtime.h>
#include <cstdint>

#define Bn 16
#define Cn 64
#define Hn 160
#define Wn 160
#define HP 161          // H+1 shifted-grid rows
#define WP 161          // W+1 shifted-grid cols
#define TJ 64           // j-tile per block
#define JT 3            // ceil(161/64)
#define NLOG 9
#define CONV_BLOCKS (Bn * HP * JT)
#define WT_STRIDE 66    // padded smem stride for transposed W (even -> float2 aligned, conflict-lite)
#define LU_STRIDE 65

__device__ double g_dlog[NLOG];

__device__ __forceinline__ float2 ffma2(float2 a, float2 b, float2 c) {
    unsigned long long A = *reinterpret_cast<unsigned long long*>(&a);
    unsigned long long Bv = *reinterpret_cast<unsigned long long*>(&b);
    unsigned long long Cv = *reinterpret_cast<unsigned long long*>(&c);
    unsigned long long D;
    asm("fma.rn.f32x2 %0, %1, %2, %3;" : "=l"(D) : "l"(A), "l"(Bv), "l"(Cv));
    return *reinterpret_cast<float2*>(&D);
}

// ---------------- logdet blocks (blocks 0..8 of the main grid) ----------------
__device__ void logdet_block(int r, const float* __restrict__ wgt, unsigned char* smem_raw) {
    double* A = reinterpret_cast<double*>(smem_raw);  // [n][LU_STRIDE]
    __shared__ double s_val[2];
    __shared__ int    s_idx[2];
    __shared__ int    s_piv;
    __shared__ double s_acc;

    const int tid = threadIdx.x;
    const int n   = (r == 0) ? 64 : (r <= 4 ? 32 : 16);
    const double pixw = (r == 0) ? (double)(Hn - 1) * (double)(Wn - 1)
                                 : (r <= 4 ? (double)(Wn - 1) : 1.0);

    // channel index maps (np.ix_ keeps ascending order within each mask)
    auto chan = [&](int m) -> int {
        if (r == 0) return m;
        if (r <= 4) {
            // t:{2,3} b:{0,1} l:{1,3} r:{0,2}
            const int t2[4][2] = {{2, 3}, {0, 1}, {1, 3}, {0, 2}};
            return 4 * (m >> 1) + t2[r - 1][m & 1];
        }
        const int t1[4] = {3, 2, 1, 0};  // tl,tr,bl,br
        return 4 * m + t1[r - 5];
    };

    for (int idx = tid; idx < n * n; idx += 128) {
        int ri = idx / n, ci = idx % n;
        A[ri * LU_STRIDE + ci] = (double)wgt[chan(ri) * Cn + chan(ci)];
    }
    if (tid == 0) s_acc = 0.0;
    __syncthreads();

    for (int k = 0; k < n; k++) {
        // parallel partial-pivot search over rows k..n-1
        double v = -1.0;
        int vi = tid;
        if (tid >= k && tid < n) v = fabs(A[tid * LU_STRIDE + k]);
        if (tid < 64) {
#pragma unroll
            for (int off = 16; off; off >>= 1) {
                double ov = __shfl_down_sync(0xffffffffu, v, off);
                int    oi = __shfl_down_sync(0xffffffffu, vi, off);
                if (ov > v) { v = ov; vi = oi; }
            }
            if ((tid & 31) == 0) { s_val[tid >> 5] = v; s_idx[tid >> 5] = vi; }
        }
        __syncthreads();
        if (tid == 0) {
            double bv = s_val[0]; int bi = s_idx[0];
            if (n > 32 && s_val[1] > bv) { bv = s_val[1]; bi = s_idx[1]; }
            s_piv = bi;
            s_acc += log(bv);   // log|pivot|; sign irrelevant for slogdet[1]
        }
        __syncthreads();
        const int piv = s_piv;
        if (piv != k && tid < n) {
            double t = A[k * LU_STRIDE + tid];
            A[k * LU_STRIDE + tid]   = A[piv * LU_STRIDE + tid];
            A[piv * LU_STRIDE + tid] = t;
        }
        __syncthreads();
        if (tid > k && tid < n) {
            double m = A[tid * LU_STRIDE + k] / A[k * LU_STRIDE + k];
            for (int c = k + 1; c < n; c++)
                A[tid * LU_STRIDE + c] -= m * A[k * LU_STRIDE + c];
        }
        __syncthreads();
    }
    if (tid == 0) g_dlog[r] = s_acc * pixw;
}

// ---------------- main kernel: unified gather -> 64x64 matvec -> scatter ----------------
extern "C" __global__ void __launch_bounds__(128)
ic1x1_main_kernel(const float* __restrict__ x, const float* __restrict__ wgt,
                  float* __restrict__ out)
{
    __shared__ __align__(16) unsigned char smem_raw[33280];

    const int bx = blockIdx.x;
    if (bx < NLOG) { logdet_block(bx, wgt, smem_raw); return; }

    const int id = bx - NLOG;
    const int jt = id % JT;
    const int i  = (id / JT) % HP;
    const int b  = id / (JT * HP);
    const int j0 = jt * TJ;

    float* wt  = reinterpret_cast<float*>(smem_raw);  // transposed W: wt[k][co], stride 66
    float* zsh = wt + 64 * WT_STRIDE;                 // gathered tile: zsh[k][jj], 64x64

    const int tid = threadIdx.x;

    // load W coalesced, store transposed (wt[k*66+co] = W[co][k])
#pragma unroll
    for (int n = 0; n < 32; n++) {
        int idx = tid + n * 128;
        int co = idx >> 6;
        int k  = idx & 63;
        wt[k * WT_STRIDE + co] = wgt[idx];
    }
    // gather the shifted-grid tile (uniform boundary rule == region masks)
#pragma unroll
    for (int n = 0; n < 32; n++) {
        int idx = tid + n * 128;
        int k  = idx >> 6;   // c_in
        int jj = idx & 63;
        int p = (k >> 1) & 1, q = k & 1;
        int pp = 1 - p, qq = 1 - q;
        int sc = (k & ~3) | (pp << 1) | qq;   // flipped source channel
        int si = i - pp;
        int sj = j0 + jj - qq;
        float v = 0.0f;
        if ((unsigned)si < (unsigned)Hn && (unsigned)sj < (unsigned)Wn)
            v = x[((b * Cn + sc) * Hn + si) * Wn + sj];
        zsh[k * 64 + jj] = v;
    }
    __syncthreads();

    const int tr = tid >> 4;   // c_out group (8 c_out each)
    const int tc = tid & 15;   // j lane (4 j each, stride 16)

    float2 acc[4][4];
#pragma unroll
    for (int u = 0; u < 4; u++)
#pragma unroll
        for (int rr = 0; rr < 4; rr++) acc[u][rr] = make_float2(0.0f, 0.0f);

    const float* wrow = wt + tr * 8;
    const float* zcol = zsh + tc;

#pragma unroll 8
    for (int k = 0; k < 64; k++) {
        float2 w0 = *reinterpret_cast<const float2*>(wrow + k * WT_STRIDE + 0);
        float2 w1 = *reinterpret_cast<const float2*>(wrow + k * WT_STRIDE + 2);
        float2 w2 = *reinterpret_cast<const float2*>(wrow + k * WT_STRIDE + 4);
        float2 w3 = *reinterpret_cast<const float2*>(wrow + k * WT_STRIDE + 6);
#pragma unroll
        for (int rr = 0; rr < 4; rr++) {
            float zv = zcol[k * 64 + 16 * rr];
            float2 zz = make_float2(zv, zv);
            acc[0][rr] = ffma2(w0, zz, acc[0][rr]);
            acc[1][rr] = ffma2(w1, zz, acc[1][rr]);
            acc[2][rr] = ffma2(w2, zz, acc[2][rr]);
            acc[3][rr] = ffma2(w3, zz, acc[3][rr]);
        }
    }

    // scatter through the inverse shift (predication == output region masks)
#pragma unroll
    for (int u = 0; u < 4; u++) {
#pragma unroll
        for (int h = 0; h < 2; h++) {
            int co = tr * 8 + 2 * u + h;
            int P = (co >> 1) & 1, Q = co & 1;
            int dc = (co & ~3) | ((1 - P) << 1) | (1 - Q);
            int di = i - (1 - P);
            if ((unsigned)di >= (unsigned)Hn) continue;
            float* orow = out + ((b * Cn + dc) * Hn + di) * Wn;
#pragma unroll
            for (int rr = 0; rr < 4; rr++) {
                int j  = j0 + tc + 16 * rr;
                int dj = j - (1 - Q);
                if ((unsigned)dj < (unsigned)Wn)
                    orow[dj] = h ? acc[u][rr].y : acc[u][rr].x;
            }
        }
    }
}

extern "C" __global__ void ic1x1_fin_kernel(const float* __restrict__ ldin,
                                            float* __restrict__ outld)
{
    int t = threadIdx.x;
    if (t < Bn) {
        double s = 0.0;
#pragma unroll
        for (int k = 0; k < NLOG; k++) s += g_dlog[k];
        outld[t] = ldin[t] + (float)s;
    }
}

extern "C" void kernel_launch(void* const* d_in, const int* in_sizes, int n_in,
                              void* d_out, int out_size)
{
    const float *x = nullptr, *ld = nullptr, *w = nullptr;
    for (int k = 0; k < n_in; k++) {
        if (in_sizes[k] == Cn * Cn)      w  = (const float*)d_in[k];
        else if (in_sizes[k] == Bn)      ld = (const float*)d_in[k];
        else                             x  = (const float*)d_in[k];
    }
    float* out   = (float*)d_out;
    float* outld = out + (out_size - Bn);   // tuple layout: big tensor then 16 logdets

    ic1x1_main_kernel<<<NLOG + CONV_BLOCKS, 128>>>(x, w, out);
    ic1x1_fin_kernel<<<1, 32>>>(ld, outld);
}